// round 2
// baseline (speedup 1.0000x reference)
#include <cuda_runtime.h>

// Hamilton product of quaternions packed in the last dim (w, x, y, z).
// Shapes: q1, q2: (32, 4096, 64, 4) fp32 -> 8,388,608 quaternions.
// HBM-bound streaming op. 4 quaternions per thread, front-batched LDG.128
// (MLP_p1 = 8) to maximize L1tex queue utilization at the DRAM ceiling.

#define QPT 4  // quaternions per thread

__device__ __forceinline__ float4 hprod(float4 a, float4 b) {
    float4 r;
    r.x = a.x * b.x - a.y * b.y - a.z * b.z - a.w * b.w;  // w
    r.y = a.x * b.y + a.y * b.x + a.z * b.w - a.w * b.z;  // x
    r.z = a.x * b.z - a.y * b.w + a.z * b.x + a.w * b.y;  // y
    r.w = a.x * b.w + a.y * b.z - a.z * b.y + a.w * b.x;  // z
    return r;
}

__global__ void __launch_bounds__(256) hamilton_kernel(
    const float4* __restrict__ q1,
    const float4* __restrict__ q2,
    float4* __restrict__ out,
    int n_quat)
{
    // Contiguous-per-thread layout would break coalescing; instead use
    // block-strided chunks: thread t in block b handles indices
    // base + k*blockDim for k in [0, QPT), all lanes adjacent -> coalesced.
    int base = blockIdx.x * (blockDim.x * QPT) + threadIdx.x;

    float4 a[QPT], b[QPT];

    if (base + (QPT - 1) * 256 < n_quat) {
        // Fast path: fully in range, front-batch all 8 loads.
#pragma unroll
        for (int k = 0; k < QPT; k++) a[k] = q1[base + k * 256];
#pragma unroll
        for (int k = 0; k < QPT; k++) b[k] = q2[base + k * 256];
#pragma unroll
        for (int k = 0; k < QPT; k++) out[base + k * 256] = hprod(a[k], b[k]);
    } else {
#pragma unroll
        for (int k = 0; k < QPT; k++) {
            int i = base + k * 256;
            if (i < n_quat) out[i] = hprod(q1[i], q2[i]);
        }
    }
}

extern "C" void kernel_launch(void* const* d_in, const int* in_sizes, int n_in,
                              void* d_out, int out_size) {
    const float4* q1 = (const float4*)d_in[0];
    const float4* q2 = (const float4*)d_in[1];
    float4* out = (float4*)d_out;

    int n_quat = in_sizes[0] / 4;  // 8,388,608

    int threads = 256;
    int per_block = threads * QPT;
    int blocks = (n_quat + per_block - 1) / per_block;  // 8192
    hamilton_kernel<<<blocks, threads>>>(q1, q2, out, n_quat);
}